// round 15
// baseline (speedup 1.0000x reference)
#include <cuda_runtime.h>
#include <cuda_bf16.h>
#include <cuda_fp16.h>
#include <cstdint>

#define N_NODES 50000
#define N_EDGES 800000
#define DIM     128
#define LN_EPS  1e-5f
#define BUCKET  64          // max in-degree capacity (Poisson(16): max ~50)

typedef unsigned int u32;

// ---------------- device scratch ----------------
__device__ __half g_h[N_NODES * DIM];       // post-GEMM features (fp16)
__device__ float  g_buf[N_NODES * DIM];     // layer-1 output (fp32, GEMM2 input)
__device__ int    g_cursor[N_NODES];        // per-node fill cursor == degree
__device__ int2   g_edge[N_NODES * BUCKET]; // bucketed {src*32 (uint2-row idx), bitcast ew}
__device__ uint2  g_Wf1[2 * 8 * 16 * 32];
__device__ uint2  g_Wf2[2 * 8 * 16 * 32];

__device__ __forceinline__ u32 pack_bf16x2(float a, float b) {
    u32 lo = (u32)__bfloat16_as_ushort(__float2bfloat16(a));
    u32 hi = (u32)__bfloat16_as_ushort(__float2bfloat16(b));
    return lo | (hi << 16);
}
__device__ __forceinline__ float bf_resid(float a) {
    return a - __bfloat162float(__float2bfloat16(a));
}
__device__ __forceinline__ u32 pack_half2(float a, float b) {
    __half2 h = __float22half2_rn(make_float2(a, b));
    return *(u32*)&h;
}

// ---------------- W -> fragment images (both layers, one launch) ----------------
__global__ void conv_w_kernel(const float* __restrict__ W1,
                              const float* __restrict__ W2,
                              uint2* __restrict__ Wf1,
                              uint2* __restrict__ Wf2) {
    int gi = blockIdx.x * blockDim.x + threadIdx.x;   // 0..16383
    if (gi >= 16384) return;
    const float* W = (gi < 8192) ? W1 : W2;
    uint2* Wf      = (gi < 8192) ? Wf1 : Wf2;
    int i = gi & 8191;
    int lane = i & 31;
    int nt   = (i >> 5) & 15;
    int kc   = (i >> 9) & 7;
    int hl   = i >> 12;
    int tg = lane >> 2, tq = lane & 3;
    int n  = nt * 8 + tg;
    int kb = kc * 16 + tq * 2;
    float w0 = W[(kb + 0) * DIM + n];
    float w1 = W[(kb + 1) * DIM + n];
    float w8 = W[(kb + 8) * DIM + n];
    float w9 = W[(kb + 9) * DIM + n];
    if (hl) { w0 = bf_resid(w0); w1 = bf_resid(w1); w8 = bf_resid(w8); w9 = bf_resid(w9); }
    Wf[i] = make_uint2(pack_bf16x2(w0, w1), pack_bf16x2(w8, w9));
}

// ---------------- tensor-core GEMM: H(fp16) = X @ W (bf16 hi/lo split) ----------------
__device__ __forceinline__ void mma16816(float* c, const u32* a, uint2 b) {
    asm volatile(
        "mma.sync.aligned.m16n8k16.row.col.f32.bf16.bf16.f32 "
        "{%0,%1,%2,%3}, {%4,%5,%6,%7}, {%8,%9}, {%0,%1,%2,%3};"
        : "+f"(c[0]), "+f"(c[1]), "+f"(c[2]), "+f"(c[3])
        : "r"(a[0]), "r"(a[1]), "r"(a[2]), "r"(a[3]), "r"(b.x), "r"(b.y));
}

__global__ void __launch_bounds__(256, 2) gemm_mma_kernel(
        const float* __restrict__ X, const uint2* __restrict__ Wf,
        u32* __restrict__ Hh, int nrows) {
    int tid = threadIdx.x, w = tid >> 5, lane = tid & 31;
    int tg = lane >> 2, tq = lane & 3;
    int rowBase = blockIdx.x * 128 + w * 16;
    int r0 = rowBase + tg, r1 = r0 + 8;
    int r0c = min(r0, nrows - 1), r1c = min(r1, nrows - 1);
    const float* X0 = X + (size_t)r0c * DIM;
    const float* X1 = X + (size_t)r1c * DIM;

    float acc[16][4];
    #pragma unroll
    for (int nt = 0; nt < 16; ++nt)
        #pragma unroll
        for (int c = 0; c < 4; ++c) acc[nt][c] = 0.f;

    #pragma unroll
    for (int kc = 0; kc < 8; ++kc) {
        int c0 = kc * 16 + tq * 2;
        float2 x00 = *(const float2*)(X0 + c0);
        float2 x01 = *(const float2*)(X0 + c0 + 8);
        float2 x10 = *(const float2*)(X1 + c0);
        float2 x11 = *(const float2*)(X1 + c0 + 8);
        u32 ahi[4], alo[4];
        ahi[0] = pack_bf16x2(x00.x, x00.y);
        ahi[1] = pack_bf16x2(x10.x, x10.y);
        ahi[2] = pack_bf16x2(x01.x, x01.y);
        ahi[3] = pack_bf16x2(x11.x, x11.y);
        alo[0] = pack_bf16x2(bf_resid(x00.x), bf_resid(x00.y));
        alo[1] = pack_bf16x2(bf_resid(x10.x), bf_resid(x10.y));
        alo[2] = pack_bf16x2(bf_resid(x01.x), bf_resid(x01.y));
        alo[3] = pack_bf16x2(bf_resid(x11.x), bf_resid(x11.y));

        const uint2* bh = Wf + ((size_t)(0 * 8 + kc) * 16) * 32 + lane;
        const uint2* bl = Wf + ((size_t)(1 * 8 + kc) * 16) * 32 + lane;
        #pragma unroll
        for (int nt = 0; nt < 16; ++nt) {
            uint2 bhv = __ldg(bh + nt * 32);
            uint2 blv = __ldg(bl + nt * 32);
            mma16816(acc[nt], ahi, bhv);
            mma16816(acc[nt], ahi, blv);
            mma16816(acc[nt], alo, bhv);
        }
    }

    #pragma unroll
    for (int nt = 0; nt < 16; ++nt) {
        int col = nt * 8 + tq * 2;
        if (r0 < nrows)
            Hh[(size_t)r0 * 64 + (col >> 1)] = pack_half2(acc[nt][0], acc[nt][1]);
        if (r1 < nrows)
            Hh[(size_t)r1 * 64 + (col >> 1)] = pack_half2(acc[nt][2], acc[nt][3]);
    }
}

// ---------------- bucketed CSR build: single scatter pass ----------------
// Stores PRESCALED src index (src*32 = uint2-row offset) to kill gather IMADs.
__global__ void fill_kernel(const int* __restrict__ eidx,
                            const float* __restrict__ ew, int E) {
    int e4 = blockIdx.x * blockDim.x + threadIdx.x;
    if (e4 < E / 4) {
        int4   s = __ldg(&((const int4*)eidx)[e4]);
        int4   d = __ldg(&((const int4*)(eidx + E))[e4]);
        float4 w = __ldg(&((const float4*)ew)[e4]);
        int p0 = atomicAdd(&g_cursor[d.x], 1);
        int p1 = atomicAdd(&g_cursor[d.y], 1);
        int p2 = atomicAdd(&g_cursor[d.z], 1);
        int p3 = atomicAdd(&g_cursor[d.w], 1);
        g_edge[d.x * BUCKET + p0] = make_int2(s.x * 32, __float_as_int(w.x));
        g_edge[d.y * BUCKET + p1] = make_int2(s.y * 32, __float_as_int(w.y));
        g_edge[d.z * BUCKET + p2] = make_int2(s.z * 32, __float_as_int(w.z));
        g_edge[d.w * BUCKET + p3] = make_int2(s.w * 32, __float_as_int(w.w));
    }
}

// ---------------- Aggregate(fp16) + bias + LayerNorm + ReLU ----------------
// One warp per node (R13 proven form); int4 edge loads, prescaled gather index.
__global__ __launch_bounds__(256) void agg_ln_relu_kernel(
        const u32* __restrict__ Hh,
        const float* __restrict__ bias,
        const float* __restrict__ gamma,
        const float* __restrict__ beta,
        float* __restrict__ out, int nrows) {
    int w = threadIdx.x >> 5, lane = threadIdx.x & 31;
    int node = blockIdx.x * 8 + w;
    if (node >= nrows) return;

    int jb  = node * BUCKET;
    int deg = __ldg(&g_cursor[node]);
    int je  = jb + deg;
    const uint2* Hv = (const uint2*)Hh;

    float4 acc = make_float4(0.f, 0.f, 0.f, 0.f);
    int j = jb;
    for (; j + 8 <= je; j += 8) {
        int4 q[4];
        #pragma unroll
        for (int u = 0; u < 4; ++u)
            q[u] = __ldg((const int4*)(g_edge + j) + u);   // 2 edges per LDG.128
        u32 idx[8]; float ew8[8];
        idx[0] = (u32)q[0].x; ew8[0] = __int_as_float(q[0].y);
        idx[1] = (u32)q[0].z; ew8[1] = __int_as_float(q[0].w);
        idx[2] = (u32)q[1].x; ew8[2] = __int_as_float(q[1].y);
        idx[3] = (u32)q[1].z; ew8[3] = __int_as_float(q[1].w);
        idx[4] = (u32)q[2].x; ew8[4] = __int_as_float(q[2].y);
        idx[5] = (u32)q[2].z; ew8[5] = __int_as_float(q[2].w);
        idx[6] = (u32)q[3].x; ew8[6] = __int_as_float(q[3].y);
        idx[7] = (u32)q[3].z; ew8[7] = __int_as_float(q[3].w);
        uint2 hv[8];
        #pragma unroll
        for (int u = 0; u < 8; ++u)
            hv[u] = __ldg(&Hv[idx[u] + lane]);   // IADD + IMAD.WIDE only
        #pragma unroll
        for (int u = 0; u < 8; ++u) {
            float e = ew8[u];
            float2 f01 = __half22float2(*(__half2*)&hv[u].x);
            float2 f23 = __half22float2(*(__half2*)&hv[u].y);
            acc.x += e * f01.x; acc.y += e * f01.y;
            acc.z += e * f23.x; acc.w += e * f23.y;
        }
    }
    for (; j < je; ++j) {
        int2 p = __ldg(&g_edge[j]);
        float e = __int_as_float(p.y);
        uint2 hv = __ldg(&Hv[(u32)p.x + lane]);
        float2 f01 = __half22float2(*(__half2*)&hv.x);
        float2 f23 = __half22float2(*(__half2*)&hv.y);
        acc.x += e * f01.x; acc.y += e * f01.y;
        acc.z += e * f23.x; acc.w += e * f23.y;
    }

    float4 b4 = __ldg(&((const float4*)bias)[lane]);
    acc.x += b4.x; acc.y += b4.y; acc.z += b4.z; acc.w += b4.w;

    float s1 = acc.x + acc.y + acc.z + acc.w;
    float s2 = acc.x * acc.x + acc.y * acc.y + acc.z * acc.z + acc.w * acc.w;
    #pragma unroll
    for (int o = 16; o > 0; o >>= 1) {
        s1 += __shfl_xor_sync(0xffffffffu, s1, o);
        s2 += __shfl_xor_sync(0xffffffffu, s2, o);
    }
    float mu  = s1 * (1.f / 128.f);
    float var = s2 * (1.f / 128.f) - mu * mu;
    float r   = rsqrtf(var + LN_EPS);

    float4 g4 = __ldg(&((const float4*)gamma)[lane]);
    float4 e4 = __ldg(&((const float4*)beta)[lane]);
    float4 y;
    y.x = fmaxf((acc.x - mu) * r * g4.x + e4.x, 0.f);
    y.y = fmaxf((acc.y - mu) * r * g4.y + e4.y, 0.f);
    y.z = fmaxf((acc.z - mu) * r * g4.z + e4.z, 0.f);
    y.w = fmaxf((acc.w - mu) * r * g4.w + e4.w, 0.f);
    ((float4*)(out + (size_t)node * DIM))[lane] = y;
}

// ---------------- launch: fork (memset->fill) || (conv_w -> gemm1) ----------------
extern "C" void kernel_launch(void* const* d_in, const int* in_sizes, int n_in,
                              void* d_out, int out_size) {
    const float* x    = (const float*)d_in[0];
    const int*   eidx = (const int*)d_in[1];
    const float* ew   = (const float*)d_in[2];
    const float* W1   = (const float*)d_in[3];
    const float* b1   = (const float*)d_in[4];
    const float* W2   = (const float*)d_in[5];
    const float* b2   = (const float*)d_in[6];
    const float* g1   = (const float*)d_in[7];
    const float* be1  = (const float*)d_in[8];
    const float* g2   = (const float*)d_in[9];
    const float* be2  = (const float*)d_in[10];
    float* out = (float*)d_out;

    const int N = N_NODES;
    const int E = N_EDGES;

    u32   *h_p;
    float *buf_p;
    int   *cur_p;
    uint2 *wf1, *wf2;
    cudaGetSymbolAddress((void**)&h_p,   g_h);
    cudaGetSymbolAddress((void**)&buf_p, g_buf);
    cudaGetSymbolAddress((void**)&cur_p, g_cursor);
    cudaGetSymbolAddress((void**)&wf1,   g_Wf1);
    cudaGetSymbolAddress((void**)&wf2,   g_Wf2);

    static cudaStream_t sB = nullptr;
    static cudaEvent_t  evRoot = nullptr, evB = nullptr;
    if (!sB) {
        cudaStreamCreateWithFlags(&sB, cudaStreamNonBlocking);
        cudaEventCreateWithFlags(&evRoot, cudaEventDisableTiming);
        cudaEventCreateWithFlags(&evB,    cudaEventDisableTiming);
    }

    const int tiles      = (N + 127) / 128;
    const int agg_blocks = (N + 7) / 8;

    // fork: side stream does conv_w + gemm1 (independent of CSR)
    cudaEventRecord(evRoot, 0);
    cudaStreamWaitEvent(sB, evRoot, 0);
    conv_w_kernel<<<64, 256, 0, sB>>>(W1, W2, wf1, wf2);
    gemm_mma_kernel<<<tiles, 256, 0, sB>>>(x, wf1, h_p, N);
    cudaEventRecord(evB, sB);

    // main stream: bucketed CSR build (2 steps only)
    cudaMemsetAsync(cur_p, 0, N * sizeof(int));
    fill_kernel<<<(E / 4 + 255) / 256, 256>>>(eidx, ew, E);

    // join, then the dependent chain
    cudaStreamWaitEvent(0, evB, 0);
    agg_ln_relu_kernel<<<agg_blocks, 256>>>(h_p, b1, g1, be1, buf_p, N);
    gemm_mma_kernel<<<tiles, 256>>>(buf_p, wf2, h_p, N);
    agg_ln_relu_kernel<<<agg_blocks, 256>>>(h_p, b2, g2, be2, out, N);
}

// round 16
// speedup vs baseline: 1.0506x; 1.0506x over previous
#include <cuda_runtime.h>
#include <cuda_bf16.h>
#include <cuda_fp16.h>
#include <cstdint>

#define N_NODES 50000
#define N_EDGES 800000
#define DIM     128
#define LN_EPS  1e-5f
#define BUCKET  64          // max in-degree capacity (Poisson(16): max ~50)
#define SPLIT   25088       // agg1/gemm2 pipeline split (multiple of 128 and 8)

typedef unsigned int u32;

// ---------------- device scratch ----------------
__device__ __half g_h[N_NODES * DIM];       // layer-1 GEMM output (fp16)
__device__ __half g_h2[N_NODES * DIM];      // layer-2 GEMM output (fp16)
__device__ float  g_buf[N_NODES * DIM];     // layer-1 block output (fp32)
__device__ int    g_cursor[N_NODES];        // per-node fill cursor == degree
__device__ int2   g_edge[N_NODES * BUCKET]; // bucketed {src*32 (uint2-row idx), bitcast ew}
__device__ uint2  g_Wf1[2 * 8 * 16 * 32];
__device__ uint2  g_Wf2[2 * 8 * 16 * 32];

__device__ __forceinline__ u32 pack_bf16x2(float a, float b) {
    u32 lo = (u32)__bfloat16_as_ushort(__float2bfloat16(a));
    u32 hi = (u32)__bfloat16_as_ushort(__float2bfloat16(b));
    return lo | (hi << 16);
}
__device__ __forceinline__ float bf_resid(float a) {
    return a - __bfloat162float(__float2bfloat16(a));
}
__device__ __forceinline__ u32 pack_half2(float a, float b) {
    __half2 h = __float22half2_rn(make_float2(a, b));
    return *(u32*)&h;
}

// ---------------- W -> fragment images (both layers, one launch) ----------------
__global__ void conv_w_kernel(const float* __restrict__ W1,
                              const float* __restrict__ W2,
                              uint2* __restrict__ Wf1,
                              uint2* __restrict__ Wf2) {
    int gi = blockIdx.x * blockDim.x + threadIdx.x;   // 0..16383
    if (gi >= 16384) return;
    const float* W = (gi < 8192) ? W1 : W2;
    uint2* Wf      = (gi < 8192) ? Wf1 : Wf2;
    int i = gi & 8191;
    int lane = i & 31;
    int nt   = (i >> 5) & 15;
    int kc   = (i >> 9) & 7;
    int hl   = i >> 12;
    int tg = lane >> 2, tq = lane & 3;
    int n  = nt * 8 + tg;
    int kb = kc * 16 + tq * 2;
    float w0 = W[(kb + 0) * DIM + n];
    float w1 = W[(kb + 1) * DIM + n];
    float w8 = W[(kb + 8) * DIM + n];
    float w9 = W[(kb + 9) * DIM + n];
    if (hl) { w0 = bf_resid(w0); w1 = bf_resid(w1); w8 = bf_resid(w8); w9 = bf_resid(w9); }
    Wf[i] = make_uint2(pack_bf16x2(w0, w1), pack_bf16x2(w8, w9));
}

// ---------------- tensor-core GEMM: H(fp16) = X @ W (bf16 hi/lo split) ----------------
__device__ __forceinline__ void mma16816(float* c, const u32* a, uint2 b) {
    asm volatile(
        "mma.sync.aligned.m16n8k16.row.col.f32.bf16.bf16.f32 "
        "{%0,%1,%2,%3}, {%4,%5,%6,%7}, {%8,%9}, {%0,%1,%2,%3};"
        : "+f"(c[0]), "+f"(c[1]), "+f"(c[2]), "+f"(c[3])
        : "r"(a[0]), "r"(a[1]), "r"(a[2]), "r"(a[3]), "r"(b.x), "r"(b.y));
}

__global__ void __launch_bounds__(256, 2) gemm_mma_kernel(
        const float* __restrict__ X, const uint2* __restrict__ Wf,
        u32* __restrict__ Hh, int rowStart, int nrows) {
    int tid = threadIdx.x, w = tid >> 5, lane = tid & 31;
    int tg = lane >> 2, tq = lane & 3;
    int rowBase = rowStart + blockIdx.x * 128 + w * 16;
    int r0 = rowBase + tg, r1 = r0 + 8;
    int r0c = min(r0, nrows - 1), r1c = min(r1, nrows - 1);
    const float* X0 = X + (size_t)r0c * DIM;
    const float* X1 = X + (size_t)r1c * DIM;

    float acc[16][4];
    #pragma unroll
    for (int nt = 0; nt < 16; ++nt)
        #pragma unroll
        for (int c = 0; c < 4; ++c) acc[nt][c] = 0.f;

    #pragma unroll
    for (int kc = 0; kc < 8; ++kc) {
        int c0 = kc * 16 + tq * 2;
        float2 x00 = *(const float2*)(X0 + c0);
        float2 x01 = *(const float2*)(X0 + c0 + 8);
        float2 x10 = *(const float2*)(X1 + c0);
        float2 x11 = *(const float2*)(X1 + c0 + 8);
        u32 ahi[4], alo[4];
        ahi[0] = pack_bf16x2(x00.x, x00.y);
        ahi[1] = pack_bf16x2(x10.x, x10.y);
        ahi[2] = pack_bf16x2(x01.x, x01.y);
        ahi[3] = pack_bf16x2(x11.x, x11.y);
        alo[0] = pack_bf16x2(bf_resid(x00.x), bf_resid(x00.y));
        alo[1] = pack_bf16x2(bf_resid(x10.x), bf_resid(x10.y));
        alo[2] = pack_bf16x2(bf_resid(x01.x), bf_resid(x01.y));
        alo[3] = pack_bf16x2(bf_resid(x11.x), bf_resid(x11.y));

        const uint2* bh = Wf + ((size_t)(0 * 8 + kc) * 16) * 32 + lane;
        const uint2* bl = Wf + ((size_t)(1 * 8 + kc) * 16) * 32 + lane;
        #pragma unroll
        for (int nt = 0; nt < 16; ++nt) {
            uint2 bhv = __ldg(bh + nt * 32);
            uint2 blv = __ldg(bl + nt * 32);
            mma16816(acc[nt], ahi, bhv);
            mma16816(acc[nt], ahi, blv);
            mma16816(acc[nt], alo, bhv);
        }
    }

    #pragma unroll
    for (int nt = 0; nt < 16; ++nt) {
        int col = nt * 8 + tq * 2;
        if (r0 < nrows)
            Hh[(size_t)r0 * 64 + (col >> 1)] = pack_half2(acc[nt][0], acc[nt][1]);
        if (r1 < nrows)
            Hh[(size_t)r1 * 64 + (col >> 1)] = pack_half2(acc[nt][2], acc[nt][3]);
    }
}

// ---------------- bucketed CSR build: single scatter pass ----------------
// Stores PRESCALED src index (src*32 = uint2-row offset).
__global__ void fill_kernel(const int* __restrict__ eidx,
                            const float* __restrict__ ew, int E) {
    int e4 = blockIdx.x * blockDim.x + threadIdx.x;
    if (e4 < E / 4) {
        int4   s = __ldg(&((const int4*)eidx)[e4]);
        int4   d = __ldg(&((const int4*)(eidx + E))[e4]);
        float4 w = __ldg(&((const float4*)ew)[e4]);
        int p0 = atomicAdd(&g_cursor[d.x], 1);
        int p1 = atomicAdd(&g_cursor[d.y], 1);
        int p2 = atomicAdd(&g_cursor[d.z], 1);
        int p3 = atomicAdd(&g_cursor[d.w], 1);
        g_edge[d.x * BUCKET + p0] = make_int2(s.x * 32, __float_as_int(w.x));
        g_edge[d.y * BUCKET + p1] = make_int2(s.y * 32, __float_as_int(w.y));
        g_edge[d.z * BUCKET + p2] = make_int2(s.z * 32, __float_as_int(w.z));
        g_edge[d.w * BUCKET + p3] = make_int2(s.w * 32, __float_as_int(w.w));
    }
}

// ---------------- Aggregate(fp16) + bias + LayerNorm + ReLU (R13 shape) ----------------
__global__ __launch_bounds__(256) void agg_ln_relu_kernel(
        const u32* __restrict__ Hh,
        const float* __restrict__ bias,
        const float* __restrict__ gamma,
        const float* __restrict__ beta,
        float* __restrict__ out, int nodeStart, int nodeEnd) {
    int w = threadIdx.x >> 5, lane = threadIdx.x & 31;
    int node = nodeStart + blockIdx.x * 8 + w;
    if (node >= nodeEnd) return;

    int jb = node * BUCKET;
    int je = jb + g_cursor[node];
    const uint2* Hv = (const uint2*)Hh;

    float4 acc = make_float4(0.f, 0.f, 0.f, 0.f);
    int j = jb;
    for (; j + 8 <= je; j += 8) {
        int2 p[8];
        #pragma unroll
        for (int u = 0; u < 8; ++u) p[u] = __ldg(&g_edge[j + u]);
        uint2 hv[8];
        #pragma unroll
        for (int u = 0; u < 8; ++u)
            hv[u] = __ldg(&Hv[(u32)p[u].x + lane]);   // prescaled: IADD only
        #pragma unroll
        for (int u = 0; u < 8; ++u) {
            float e = __int_as_float(p[u].y);
            float2 f01 = __half22float2(*(__half2*)&hv[u].x);
            float2 f23 = __half22float2(*(__half2*)&hv[u].y);
            acc.x += e * f01.x; acc.y += e * f01.y;
            acc.z += e * f23.x; acc.w += e * f23.y;
        }
    }
    for (; j < je; ++j) {
        int2 p = __ldg(&g_edge[j]);
        float e = __int_as_float(p.y);
        uint2 hv = __ldg(&Hv[(u32)p.x + lane]);
        float2 f01 = __half22float2(*(__half2*)&hv.x);
        float2 f23 = __half22float2(*(__half2*)&hv.y);
        acc.x += e * f01.x; acc.y += e * f01.y;
        acc.z += e * f23.x; acc.w += e * f23.y;
    }

    float4 b4 = __ldg(&((const float4*)bias)[lane]);
    acc.x += b4.x; acc.y += b4.y; acc.z += b4.z; acc.w += b4.w;

    float s1 = acc.x + acc.y + acc.z + acc.w;
    float s2 = acc.x * acc.x + acc.y * acc.y + acc.z * acc.z + acc.w * acc.w;
    #pragma unroll
    for (int o = 16; o > 0; o >>= 1) {
        s1 += __shfl_xor_sync(0xffffffffu, s1, o);
        s2 += __shfl_xor_sync(0xffffffffu, s2, o);
    }
    float mu  = s1 * (1.f / 128.f);
    float var = s2 * (1.f / 128.f) - mu * mu;
    float r   = rsqrtf(var + LN_EPS);

    float4 g4 = __ldg(&((const float4*)gamma)[lane]);
    float4 e4 = __ldg(&((const float4*)beta)[lane]);
    float4 y;
    y.x = fmaxf((acc.x - mu) * r * g4.x + e4.x, 0.f);
    y.y = fmaxf((acc.y - mu) * r * g4.y + e4.y, 0.f);
    y.z = fmaxf((acc.z - mu) * r * g4.z + e4.z, 0.f);
    y.w = fmaxf((acc.w - mu) * r * g4.w + e4.w, 0.f);
    ((float4*)(out + (size_t)node * DIM))[lane] = y;
}

// ---------------- launch ----------------
extern "C" void kernel_launch(void* const* d_in, const int* in_sizes, int n_in,
                              void* d_out, int out_size) {
    const float* x    = (const float*)d_in[0];
    const int*   eidx = (const int*)d_in[1];
    const float* ew   = (const float*)d_in[2];
    const float* W1   = (const float*)d_in[3];
    const float* b1   = (const float*)d_in[4];
    const float* W2   = (const float*)d_in[5];
    const float* b2   = (const float*)d_in[6];
    const float* g1   = (const float*)d_in[7];
    const float* be1  = (const float*)d_in[8];
    const float* g2   = (const float*)d_in[9];
    const float* be2  = (const float*)d_in[10];
    float* out = (float*)d_out;

    const int N = N_NODES;
    const int E = N_EDGES;

    u32   *h_p, *h2_p;
    float *buf_p;
    int   *cur_p;
    uint2 *wf1, *wf2;
    cudaGetSymbolAddress((void**)&h_p,   g_h);
    cudaGetSymbolAddress((void**)&h2_p,  g_h2);
    cudaGetSymbolAddress((void**)&buf_p, g_buf);
    cudaGetSymbolAddress((void**)&cur_p, g_cursor);
    cudaGetSymbolAddress((void**)&wf1,   g_Wf1);
    cudaGetSymbolAddress((void**)&wf2,   g_Wf2);

    static cudaStream_t sB = nullptr;
    static cudaEvent_t  evRoot = nullptr, evB = nullptr, evA1a = nullptr, evG2a = nullptr;
    if (!sB) {
        cudaStreamCreateWithFlags(&sB, cudaStreamNonBlocking);
        cudaEventCreateWithFlags(&evRoot, cudaEventDisableTiming);
        cudaEventCreateWithFlags(&evB,    cudaEventDisableTiming);
        cudaEventCreateWithFlags(&evA1a,  cudaEventDisableTiming);
        cudaEventCreateWithFlags(&evG2a,  cudaEventDisableTiming);
    }

    const int tiles    = (N + 127) / 128;            // 391
    const int tiles_a  = SPLIT / 128;                // 196
    const int tiles_b  = (N - SPLIT + 127) / 128;    // 195
    const int aggbl_a  = SPLIT / 8;                  // 3136
    const int aggbl_b  = (N - SPLIT + 7) / 8;        // 3114
    const int aggbl    = (N + 7) / 8;

    // fork: side stream does conv_w + gemm1 (independent of CSR)
    cudaEventRecord(evRoot, 0);
    cudaStreamWaitEvent(sB, evRoot, 0);
    conv_w_kernel<<<64, 256, 0, sB>>>(W1, W2, wf1, wf2);
    gemm_mma_kernel<<<tiles, 256, 0, sB>>>(x, wf1, h_p, 0, N);
    cudaEventRecord(evB, sB);

    // main stream: bucketed CSR build
    cudaMemsetAsync(cur_p, 0, N * sizeof(int));
    fill_kernel<<<(E / 4 + 255) / 256, 256>>>(eidx, ew, E);

    // join, then pipelined layer1-agg / layer2-gemm
    cudaStreamWaitEvent(0, evB, 0);
    agg_ln_relu_kernel<<<aggbl_a, 256>>>(h_p, b1, g1, be1, buf_p, 0, SPLIT);
    cudaEventRecord(evA1a, 0);

    // side: gemm2a on first half of buf, concurrent with agg1b (writes h2!)
    cudaStreamWaitEvent(sB, evA1a, 0);
    gemm_mma_kernel<<<tiles_a, 256, 0, sB>>>(buf_p, wf2, h2_p, 0, SPLIT);
    cudaEventRecord(evG2a, sB);

    // main: agg1b
    agg_ln_relu_kernel<<<aggbl_b, 256>>>(h_p, b1, g1, be1, buf_p, SPLIT, N);

    // main: gemm2b after agg1b; wait for gemm2a before final agg
    gemm_mma_kernel<<<tiles_b, 256>>>(buf_p, wf2, h2_p, SPLIT, N);
    cudaStreamWaitEvent(0, evG2a, 0);
    agg_ln_relu_kernel<<<aggbl, 256>>>(h2_p, b2, g2, be2, out, 0, N);
}